// round 3
// baseline (speedup 1.0000x reference)
#include <cuda_runtime.h>
#include <cuda_bf16.h>

#define IN_F 128
#define HID 128
#define NCTX 32
#define ALPHA 0.2f
#define NEG_INF -9000000000000000.0f
#define MAXN 20000

// Scratch (device globals — no allocation allowed)
__device__ __align__(16) float g_u_i[IN_F];       // W_i @ a_i
__device__ __align__(16) float g_u_j[IN_F];       // W_j @ a_j
__device__ float g_bias;
__device__ float g_s_i[MAXN];
__device__ float g_s_j[MAXN];

// ---------------------------------------------------------------------------
// K1: fold attention vectors through the weight matrices.
// ---------------------------------------------------------------------------
__global__ void prep_kernel(const float* __restrict__ W_i,
                            const float* __restrict__ W_j,
                            const float* __restrict__ a_w,
                            const float* __restrict__ a_b) {
    int t = threadIdx.x;  // 0..127
    float ai = 0.f, aj = 0.f;
    #pragma unroll 8
    for (int h = 0; h < HID; h++) {
        ai += W_i[t * HID + h] * a_w[h];
        aj += W_j[t * HID + h] * a_w[HID + h];
    }
    g_u_i[t] = ai;
    g_u_j[t] = aj;
    if (t == 0) g_bias = a_b[0];
}

// ---------------------------------------------------------------------------
// K2: per-node scalar scores.  s_i[n] = h[n].u_i ; s_j[n] = h[n].u_j
// ---------------------------------------------------------------------------
__global__ void score_kernel(const float* __restrict__ h_i, int N) {
    int warp = blockIdx.x * (blockDim.x >> 5) + (threadIdx.x >> 5);
    int lane = threadIdx.x & 31;
    if (warp >= N) return;
    const float4* h4 = (const float4*)h_i;
    float4 v  = h4[(size_t)warp * 32 + lane];
    float4 ui = ((const float4*)g_u_i)[lane];
    float4 uj = ((const float4*)g_u_j)[lane];
    float a = v.x * ui.x + v.y * ui.y + v.z * ui.z + v.w * ui.w;
    float b = v.x * uj.x + v.y * uj.y + v.z * uj.z + v.w * uj.w;
    #pragma unroll
    for (int o = 16; o; o >>= 1) {
        a += __shfl_xor_sync(0xffffffffu, a, o);
        b += __shfl_xor_sync(0xffffffffu, b, o);
    }
    if (lane == 0) {
        g_s_i[warp] = a;
        g_s_j[warp] = b;
    }
}

// ---------------------------------------------------------------------------
// K3 (fused): gather + softmax + weighted raw-feature sum -> smem tile,
// then out[64x128] = tile @ W_j, all in one block per 64 nodes.
// L2-bound gather overlaps FMA-bound GEMM across blocks.
// ---------------------------------------------------------------------------
__global__ __launch_bounds__(256) void fused_kernel(
    const float* __restrict__ h_i, const int* __restrict__ ctx,
    const float* __restrict__ Wj, float* __restrict__ out, int N) {
    __shared__ float gs[64][128];
    __shared__ float ws[32][128];

    int row0 = blockIdx.x * 64;
    int tid  = threadIdx.x;
    int warp = tid >> 5;
    int lane = tid & 31;

    const float4* h4 = (const float4*)h_i;

    // Phase 1: each warp gathers 8 nodes into gs rows [warp*8, warp*8+8)
    #pragma unroll
    for (int t = 0; t < 8; t++) {
        int node = row0 + warp * 8 + t;
        float4 acc = make_float4(0.f, 0.f, 0.f, 0.f);
        if (node < N) {
            int j = ctx[(size_t)node * NCTX + lane];
            bool valid = (j >= 0);

            float sj = valid ? g_s_j[j] : 0.f;
            float e = g_s_i[node] + sj + g_bias;
            e = (e > 0.f) ? e : ALPHA * e;       // leaky relu
            e = valid ? e : NEG_INF;             // mask

            float m = e;
            #pragma unroll
            for (int o = 16; o; o >>= 1) m = fmaxf(m, __shfl_xor_sync(0xffffffffu, m, o));
            float p = valid ? __expf(e - m) : 0.f;
            float s = p;
            #pragma unroll
            for (int o = 16; o; o >>= 1) s += __shfl_xor_sync(0xffffffffu, s, o);
            float w = p * ((s > 0.f) ? (1.f / s) : 0.f);

            #pragma unroll
            for (int c = 0; c < NCTX; c++) {
                float wc = __shfl_sync(0xffffffffu, w, c);
                int jc   = __shfl_sync(0xffffffffu, j, c);
                if (jc >= 0) {
                    float4 v = h4[(size_t)jc * 32 + lane];
                    acc.x = fmaf(wc, v.x, acc.x);
                    acc.y = fmaf(wc, v.y, acc.y);
                    acc.z = fmaf(wc, v.z, acc.z);
                    acc.w = fmaf(wc, v.w, acc.w);
                }
            }
        }
        ((float4*)&gs[warp * 8 + t][0])[lane] = acc;
    }

    // Phase 2: out tile = gs @ W_j
    int cg  = lane;          // col group -> cols [cg*4, cg*4+4)
    int rg  = warp;          // row group -> rows [rg*8, rg*8+8)
    int col = cg * 4;

    float acc[8][4];
    #pragma unroll
    for (int r = 0; r < 8; r++)
        #pragma unroll
        for (int q = 0; q < 4; q++) acc[r][q] = 0.f;

    for (int k0 = 0; k0 < 128; k0 += 32) {
        __syncthreads();   // first iter also covers gs writes
        for (int i = tid; i < 32 * 32; i += 256) {
            int r = i >> 5, c4 = i & 31;
            ((float4*)&ws[r][0])[c4] = ((const float4*)Wj)[(size_t)(k0 + r) * 32 + c4];
        }
        __syncthreads();
        #pragma unroll
        for (int kk = 0; kk < 32; kk++) {
            float4 wv = *(const float4*)&ws[kk][col];
            #pragma unroll
            for (int r = 0; r < 8; r++) {
                float gv = gs[rg * 8 + r][k0 + kk];   // warp-broadcast
                acc[r][0] = fmaf(gv, wv.x, acc[r][0]);
                acc[r][1] = fmaf(gv, wv.y, acc[r][1]);
                acc[r][2] = fmaf(gv, wv.z, acc[r][2]);
                acc[r][3] = fmaf(gv, wv.w, acc[r][3]);
            }
        }
    }

    #pragma unroll
    for (int r = 0; r < 8; r++) {
        int gr = row0 + rg * 8 + r;
        if (gr < N) {
            float4 o = make_float4(acc[r][0], acc[r][1], acc[r][2], acc[r][3]);
            *(float4*)&out[(size_t)gr * 128 + col] = o;
        }
    }
}

// ---------------------------------------------------------------------------
extern "C" void kernel_launch(void* const* d_in, const int* in_sizes, int n_in,
                              void* d_out, int out_size) {
    const float* h_i = (const float*)d_in[0];
    const int*   ctx = (const int*)d_in[1];     // int32
    const float* W_i = (const float*)d_in[2];
    const float* W_j = (const float*)d_in[3];
    const float* a_w = (const float*)d_in[4];
    const float* a_b = (const float*)d_in[5];
    float* out = (float*)d_out;

    int N = in_sizes[0] / IN_F;

    prep_kernel<<<1, 128>>>(W_i, W_j, a_w, a_b);

    int blocks = (N + 7) / 8;
    score_kernel<<<blocks, 256>>>(h_i, N);

    int fused_blocks = (N + 63) / 64;
    fused_kernel<<<fused_blocks, 256>>>(h_i, ctx, W_j, out, N);
}

// round 4
// speedup vs baseline: 2.1053x; 2.1053x over previous
#include <cuda_runtime.h>
#include <cuda_bf16.h>

#define IN_F 128
#define HID 128
#define NCTX 32
#define ALPHA 0.2f
#define NEG_INF -9000000000000000.0f
#define MAXN 20000

// Scratch (device globals — no allocation allowed)
__device__ __align__(16) float g_u_i[IN_F];       // W_i @ a_i
__device__ __align__(16) float g_u_j[IN_F];       // W_j @ a_j
__device__ float g_bias;
__device__ float g_s_i[MAXN];
__device__ float g_s_j[MAXN];
__device__ __align__(16) float g_feat[(size_t)MAXN * HID]; // attn-weighted raw-feature sums

// packed f32x2 helpers (Blackwell FFMA2 via PTX)
__device__ __forceinline__ unsigned long long pk2(float a, float b) {
    unsigned long long r;
    asm("mov.b64 %0, {%1, %2};" : "=l"(r) : "f"(a), "f"(b));
    return r;
}
__device__ __forceinline__ unsigned long long dup2(float a) {
    unsigned long long r;
    asm("mov.b64 %0, {%1, %1};" : "=l"(r) : "f"(a));
    return r;
}
__device__ __forceinline__ void fma2(unsigned long long& d,
                                     unsigned long long a, unsigned long long b) {
    asm("fma.rn.f32x2 %0, %1, %2, %0;" : "+l"(d) : "l"(a), "l"(b));
}
__device__ __forceinline__ void unpk2(unsigned long long v, float& x, float& y) {
    asm("mov.b64 {%0, %1}, %2;" : "=f"(x), "=f"(y) : "l"(v));
}

// ---------------------------------------------------------------------------
// K1: fold attention vectors through weights — one warp per output element,
// coalesced float4 row reads.  256 outputs (128 u_i + 128 u_j).
// ---------------------------------------------------------------------------
__global__ void prep_kernel(const float* __restrict__ W_i,
                            const float* __restrict__ W_j,
                            const float* __restrict__ a_w,
                            const float* __restrict__ a_b) {
    int warp = blockIdx.x * (blockDim.x >> 5) + (threadIdx.x >> 5);  // 0..255
    int lane = threadIdx.x & 31;
    const float* W  = (warp < 128) ? W_i : W_j;
    const float* av = (warp < 128) ? a_w : a_w + HID;
    int f = warp & 127;
    float4 w4 = ((const float4*)W)[f * 32 + lane];
    float4 a4 = ((const float4*)av)[lane];
    float s = w4.x * a4.x + w4.y * a4.y + w4.z * a4.z + w4.w * a4.w;
    #pragma unroll
    for (int o = 16; o; o >>= 1) s += __shfl_xor_sync(0xffffffffu, s, o);
    if (lane == 0) {
        if (warp < 128) g_u_i[f] = s; else g_u_j[f] = s;
    }
    if (warp == 0 && lane == 0) g_bias = a_b[0];
}

// ---------------------------------------------------------------------------
// K2: per-node scalar scores.  s_i[n] = h[n].u_i ; s_j[n] = h[n].u_j
// ---------------------------------------------------------------------------
__global__ void score_kernel(const float* __restrict__ h_i, int N) {
    int warp = blockIdx.x * (blockDim.x >> 5) + (threadIdx.x >> 5);
    int lane = threadIdx.x & 31;
    if (warp >= N) return;
    const float4* h4 = (const float4*)h_i;
    float4 v  = h4[(size_t)warp * 32 + lane];
    float4 ui = ((const float4*)g_u_i)[lane];
    float4 uj = ((const float4*)g_u_j)[lane];
    float a = v.x * ui.x + v.y * ui.y + v.z * ui.z + v.w * ui.w;
    float b = v.x * uj.x + v.y * uj.y + v.z * uj.z + v.w * uj.w;
    #pragma unroll
    for (int o = 16; o; o >>= 1) {
        a += __shfl_xor_sync(0xffffffffu, a, o);
        b += __shfl_xor_sync(0xffffffffu, b, o);
    }
    if (lane == 0) {
        g_s_i[warp] = a;
        g_s_j[warp] = b;
    }
}

// ---------------------------------------------------------------------------
// K3: gather + leaky-relu + softmax + attention-weighted raw-feature sum.
// One warp per node (standalone: full occupancy, latency hidden by warps).
// ---------------------------------------------------------------------------
__global__ void gather_kernel(const float* __restrict__ h_i,
                              const int* __restrict__ ctx, int N) {
    int warp = blockIdx.x * (blockDim.x >> 5) + (threadIdx.x >> 5);
    int lane = threadIdx.x & 31;
    if (warp >= N) return;

    int j = ctx[(size_t)warp * NCTX + lane];
    bool valid = (j >= 0);

    float sj = valid ? g_s_j[j] : 0.f;
    float e = g_s_i[warp] + sj + g_bias;
    e = (e > 0.f) ? e : ALPHA * e;       // leaky relu
    e = valid ? e : NEG_INF;             // mask

    float m = e;
    #pragma unroll
    for (int o = 16; o; o >>= 1) m = fmaxf(m, __shfl_xor_sync(0xffffffffu, m, o));
    float p = valid ? __expf(e - m) : 0.f;
    float s = p;
    #pragma unroll
    for (int o = 16; o; o >>= 1) s += __shfl_xor_sync(0xffffffffu, s, o);
    float w = p * ((s > 0.f) ? (1.f / s) : 0.f);

    float4 acc = make_float4(0.f, 0.f, 0.f, 0.f);
    const float4* h4 = (const float4*)h_i;
    #pragma unroll
    for (int c = 0; c < NCTX; c++) {
        float wc = __shfl_sync(0xffffffffu, w, c);
        int jc   = __shfl_sync(0xffffffffu, j, c);
        if (jc >= 0) {
            float4 v = h4[(size_t)jc * 32 + lane];
            acc.x = fmaf(wc, v.x, acc.x);
            acc.y = fmaf(wc, v.y, acc.y);
            acc.z = fmaf(wc, v.z, acc.z);
            acc.w = fmaf(wc, v.w, acc.w);
        }
    }
    ((float4*)g_feat)[(size_t)warp * 32 + lane] = acc;
}

// ---------------------------------------------------------------------------
// K4: out = g_feat @ W_j.  Tile 128x128, 256 threads, micro-tile 8x8 with
// packed f32x2 accumulation (FFMA2): column pairs packed into 64-bit regs.
// ---------------------------------------------------------------------------
__global__ __launch_bounds__(256) void out_gemm_kernel(
    const float* __restrict__ Wj, float* __restrict__ out, int N) {
    __shared__ float gs[128][33];    // k-chunk of A, padded (broadcast reads)
    __shared__ float ws[32][128];    // k-chunk of W

    int row0 = blockIdx.x * 128;
    int tid  = threadIdx.x;
    int rg   = tid >> 4;     // 0..15 -> rows [rg*8, rg*8+8)
    int cg   = tid & 15;     // 0..15 -> cols [cg*8, cg*8+8)

    unsigned long long acc[8][4];
    #pragma unroll
    for (int r = 0; r < 8; r++)
        #pragma unroll
        for (int q = 0; q < 4; q++) acc[r][q] = 0ull;   // {0.f,0.f}

    const float4* g4 = (const float4*)g_feat;
    const float4* w4 = (const float4*)Wj;

    for (int k0 = 0; k0 < 128; k0 += 32) {
        __syncthreads();
        // W chunk [k0..k0+32) x 128
        for (int i = tid; i < 32 * 32; i += 256) {
            int r = i >> 5, c4 = i & 31;
            ((float4*)&ws[r][0])[c4] = w4[(size_t)(k0 + r) * 32 + c4];
        }
        // A chunk: rows [row0..row0+128) x cols [k0..k0+32), padded stride 33
        for (int i = tid; i < 128 * 8; i += 256) {
            int r = i >> 3, q = i & 7;
            int gr = row0 + r;
            float4 v = make_float4(0.f, 0.f, 0.f, 0.f);
            if (gr < N) v = g4[(size_t)gr * 32 + (k0 >> 2) + q];
            gs[r][q * 4 + 0] = v.x;
            gs[r][q * 4 + 1] = v.y;
            gs[r][q * 4 + 2] = v.z;
            gs[r][q * 4 + 3] = v.w;
        }
        __syncthreads();

        #pragma unroll
        for (int kk = 0; kk < 32; kk++) {
            float4 b0 = *(const float4*)&ws[kk][cg * 8];
            float4 b1 = *(const float4*)&ws[kk][cg * 8 + 4];
            unsigned long long bv0 = pk2(b0.x, b0.y);
            unsigned long long bv1 = pk2(b0.z, b0.w);
            unsigned long long bv2 = pk2(b1.x, b1.y);
            unsigned long long bv3 = pk2(b1.z, b1.w);
            #pragma unroll
            for (int r = 0; r < 8; r++) {
                unsigned long long av = dup2(gs[rg * 8 + r][kk]);
                fma2(acc[r][0], av, bv0);
                fma2(acc[r][1], av, bv1);
                fma2(acc[r][2], av, bv2);
                fma2(acc[r][3], av, bv3);
            }
        }
    }

    #pragma unroll
    for (int r = 0; r < 8; r++) {
        int gr = row0 + rg * 8 + r;
        if (gr < N) {
            float4 o0, o1;
            unpk2(acc[r][0], o0.x, o0.y);
            unpk2(acc[r][1], o0.z, o0.w);
            unpk2(acc[r][2], o1.x, o1.y);
            unpk2(acc[r][3], o1.z, o1.w);
            *(float4*)&out[(size_t)gr * 128 + cg * 8]     = o0;
            *(float4*)&out[(size_t)gr * 128 + cg * 8 + 4] = o1;
        }
    }
}

// ---------------------------------------------------------------------------
extern "C" void kernel_launch(void* const* d_in, const int* in_sizes, int n_in,
                              void* d_out, int out_size) {
    const float* h_i = (const float*)d_in[0];
    const int*   ctx = (const int*)d_in[1];     // int32
    const float* W_i = (const float*)d_in[2];
    const float* W_j = (const float*)d_in[3];
    const float* a_w = (const float*)d_in[4];
    const float* a_b = (const float*)d_in[5];
    float* out = (float*)d_out;

    int N = in_sizes[0] / IN_F;

    prep_kernel<<<32, 256>>>(W_i, W_j, a_w, a_b);   // 256 warps, coalesced

    int blocks = (N + 7) / 8;
    score_kernel<<<blocks, 256>>>(h_i, N);
    gather_kernel<<<blocks, 256>>>(h_i, ctx, N);

    int gemm_blocks = (N + 127) / 128;
    out_gemm_kernel<<<gemm_blocks, 256>>>(W_j, out, N);
}

// round 5
// speedup vs baseline: 2.7250x; 1.2944x over previous
#include <cuda_runtime.h>
#include <cuda_bf16.h>

#define IN_F 128
#define HID 128
#define NCTX 32
#define ALPHA 0.2f
#define NEG_INF -9000000000000000.0f
#define MAXN 20000

// Scratch (device globals — no allocation allowed)
__device__ __align__(16) float g_u_i[IN_F];       // W_i @ a_i
__device__ __align__(16) float g_u_j[IN_F];       // W_j @ a_j
__device__ float g_bias;
__device__ float g_s_i[MAXN];
__device__ float g_s_j[MAXN];
__device__ __align__(16) float g_feat[(size_t)MAXN * HID]; // attn-weighted raw-feature sums

// packed f32x2 helpers (Blackwell FFMA2 via PTX)
__device__ __forceinline__ unsigned long long dup2(float a) {
    unsigned long long r;
    asm("mov.b64 %0, {%1, %1};" : "=l"(r) : "f"(a));
    return r;
}
__device__ __forceinline__ void fma2(unsigned long long& d,
                                     unsigned long long a, unsigned long long b) {
    asm("fma.rn.f32x2 %0, %1, %2, %0;" : "+l"(d) : "l"(a), "l"(b));
}
__device__ __forceinline__ void unpk2(unsigned long long v, float& x, float& y) {
    asm("mov.b64 {%0, %1}, %2;" : "=f"(x), "=f"(y) : "l"(v));
}

// ---------------------------------------------------------------------------
// K1: fold attention vectors through weights — one warp per output element.
// ---------------------------------------------------------------------------
__global__ void prep_kernel(const float* __restrict__ W_i,
                            const float* __restrict__ W_j,
                            const float* __restrict__ a_w,
                            const float* __restrict__ a_b) {
    int warp = blockIdx.x * (blockDim.x >> 5) + (threadIdx.x >> 5);  // 0..255
    int lane = threadIdx.x & 31;
    const float* W  = (warp < 128) ? W_i : W_j;
    const float* av = (warp < 128) ? a_w : a_w + HID;
    int f = warp & 127;
    float4 w4 = ((const float4*)W)[f * 32 + lane];
    float4 a4 = ((const float4*)av)[lane];
    float s = w4.x * a4.x + w4.y * a4.y + w4.z * a4.z + w4.w * a4.w;
    #pragma unroll
    for (int o = 16; o; o >>= 1) s += __shfl_xor_sync(0xffffffffu, s, o);
    if (lane == 0) {
        if (warp < 128) g_u_i[f] = s; else g_u_j[f] = s;
    }
    if (warp == 0 && lane == 0) g_bias = a_b[0];
}

// ---------------------------------------------------------------------------
// K2: per-node scalar scores.  s_i[n] = h[n].u_i ; s_j[n] = h[n].u_j
// ---------------------------------------------------------------------------
__global__ void score_kernel(const float* __restrict__ h_i, int N) {
    int warp = blockIdx.x * (blockDim.x >> 5) + (threadIdx.x >> 5);
    int lane = threadIdx.x & 31;
    if (warp >= N) return;
    const float4* h4 = (const float4*)h_i;
    float4 v  = h4[(size_t)warp * 32 + lane];
    float4 ui = ((const float4*)g_u_i)[lane];
    float4 uj = ((const float4*)g_u_j)[lane];
    float a = v.x * ui.x + v.y * ui.y + v.z * ui.z + v.w * ui.w;
    float b = v.x * uj.x + v.y * uj.y + v.z * uj.z + v.w * uj.w;
    #pragma unroll
    for (int o = 16; o; o >>= 1) {
        a += __shfl_xor_sync(0xffffffffu, a, o);
        b += __shfl_xor_sync(0xffffffffu, b, o);
    }
    if (lane == 0) {
        g_s_i[warp] = a;
        g_s_j[warp] = b;
    }
}

// ---------------------------------------------------------------------------
// K3: gather + leaky-relu + softmax + attention-weighted raw-feature sum.
// One warp per node.
// ---------------------------------------------------------------------------
__global__ void gather_kernel(const float* __restrict__ h_i,
                              const int* __restrict__ ctx, int N) {
    int warp = blockIdx.x * (blockDim.x >> 5) + (threadIdx.x >> 5);
    int lane = threadIdx.x & 31;
    if (warp >= N) return;

    int j = ctx[(size_t)warp * NCTX + lane];
    bool valid = (j >= 0);

    float sj = valid ? g_s_j[j] : 0.f;
    float e = g_s_i[warp] + sj + g_bias;
    e = (e > 0.f) ? e : ALPHA * e;       // leaky relu
    e = valid ? e : NEG_INF;             // mask

    float m = e;
    #pragma unroll
    for (int o = 16; o; o >>= 1) m = fmaxf(m, __shfl_xor_sync(0xffffffffu, m, o));
    float p = valid ? __expf(e - m) : 0.f;
    float s = p;
    #pragma unroll
    for (int o = 16; o; o >>= 1) s += __shfl_xor_sync(0xffffffffu, s, o);
    float w = p * ((s > 0.f) ? (1.f / s) : 0.f);

    float4 acc = make_float4(0.f, 0.f, 0.f, 0.f);
    const float4* h4 = (const float4*)h_i;
    #pragma unroll
    for (int c = 0; c < NCTX; c++) {
        float wc = __shfl_sync(0xffffffffu, w, c);
        int jc   = __shfl_sync(0xffffffffu, j, c);
        if (jc >= 0) {
            float4 v = h4[(size_t)jc * 32 + lane];
            acc.x = fmaf(wc, v.x, acc.x);
            acc.y = fmaf(wc, v.y, acc.y);
            acc.z = fmaf(wc, v.z, acc.z);
            acc.w = fmaf(wc, v.w, acc.w);
        }
    }
    ((float4*)g_feat)[(size_t)warp * 32 + lane] = acc;
}

// ---------------------------------------------------------------------------
// K4: out = g_feat @ W_j.  64x128 tile, 128 threads, 8x8 micro-tile, FFMA2.
// acc[r][cp] packs a column PAIR -> b operands come straight out of LDS.128
// (no packing movs); only the a-broadcast needs a dup mov.
// smem 24KB, <=128 regs, 4 blocks/SM (16 warps).
// ---------------------------------------------------------------------------
__global__ __launch_bounds__(128, 4) void out_gemm_kernel(
    const float* __restrict__ Wj, float* __restrict__ out, int N) {
    __shared__ float ws[32][128];   // W k-chunk   (16KB)
    __shared__ float gs[64][32];    // A k-chunk   (8KB)

    int row0 = blockIdx.x * 64;
    int tid  = threadIdx.x;
    int rg   = tid >> 4;     // 0..7  -> rows [rg*8, rg*8+8)
    int cg   = tid & 15;     // 0..15 -> cols [cg*8, cg*8+8)

    unsigned long long acc[8][4];
    #pragma unroll
    for (int r = 0; r < 8; r++)
        #pragma unroll
        for (int q = 0; q < 4; q++) acc[r][q] = 0ull;

    const float4* g4 = (const float4*)g_feat;
    const float4* w4 = (const float4*)Wj;

    for (int k0 = 0; k0 < 128; k0 += 32) {
        __syncthreads();
        // W chunk [k0..k0+32) x 128  (32*32 float4 / 128 thr = 8 each)
        #pragma unroll
        for (int i = tid; i < 32 * 32; i += 128) {
            int r = i >> 5, c4 = i & 31;
            ((float4*)&ws[r][0])[c4] = w4[(size_t)(k0 + r) * 32 + c4];
        }
        // A chunk rows [row0..row0+64) x k [k0..k0+32)  (64*8 float4)
        #pragma unroll
        for (int i = tid; i < 64 * 8; i += 128) {
            int r = i >> 3, q = i & 7;
            int gr = row0 + r;
            float4 v = make_float4(0.f, 0.f, 0.f, 0.f);
            if (gr < N) v = g4[(size_t)gr * 32 + (k0 >> 2) + q];
            ((float4*)&gs[r][0])[q] = v;
        }
        __syncthreads();

        #pragma unroll
        for (int kk = 0; kk < 32; kk++) {
            // b: two LDS.128 -> four packed col-pairs, no movs
            float4 b0 = *(const float4*)&ws[kk][cg * 8];
            float4 b1 = *(const float4*)&ws[kk][cg * 8 + 4];
            unsigned long long bv0 = *(const unsigned long long*)&b0.x;
            unsigned long long bv1 = *(const unsigned long long*)&b0.z;
            unsigned long long bv2 = *(const unsigned long long*)&b1.x;
            unsigned long long bv3 = *(const unsigned long long*)&b1.z;
            #pragma unroll
            for (int r = 0; r < 8; r++) {
                unsigned long long av = dup2(gs[rg * 8 + r][kk]);
                fma2(acc[r][0], av, bv0);
                fma2(acc[r][1], av, bv1);
                fma2(acc[r][2], av, bv2);
                fma2(acc[r][3], av, bv3);
            }
        }
    }

    #pragma unroll
    for (int r = 0; r < 8; r++) {
        int gr = row0 + rg * 8 + r;
        if (gr < N) {
            float4 o0, o1;
            unpk2(acc[r][0], o0.x, o0.y);
            unpk2(acc[r][1], o0.z, o0.w);
            unpk2(acc[r][2], o1.x, o1.y);
            unpk2(acc[r][3], o1.z, o1.w);
            *(float4*)&out[(size_t)gr * 128 + cg * 8]     = o0;
            *(float4*)&out[(size_t)gr * 128 + cg * 8 + 4] = o1;
        }
    }
}

// ---------------------------------------------------------------------------
extern "C" void kernel_launch(void* const* d_in, const int* in_sizes, int n_in,
                              void* d_out, int out_size) {
    const float* h_i = (const float*)d_in[0];
    const int*   ctx = (const int*)d_in[1];     // int32
    const float* W_i = (const float*)d_in[2];
    const float* W_j = (const float*)d_in[3];
    const float* a_w = (const float*)d_in[4];
    const float* a_b = (const float*)d_in[5];
    float* out = (float*)d_out;

    int N = in_sizes[0] / IN_F;

    prep_kernel<<<32, 256>>>(W_i, W_j, a_w, a_b);

    int blocks = (N + 7) / 8;
    score_kernel<<<blocks, 256>>>(h_i, N);
    gather_kernel<<<blocks, 256>>>(h_i, ctx, N);

    int gemm_blocks = (N + 63) / 64;
    out_gemm_kernel<<<gemm_blocks, 128>>>(W_j, out, N);
}